// round 4
// baseline (speedup 1.0000x reference)
#include <cuda_runtime.h>
#include <cuda_bf16.h>
#include <cstdint>

#define NTHR 320
#define GROUP 16
#define ALPHA 0.2f
#define BN_EPS 1e-5f

// ---- smem byte offsets ----
#define OFF_A1 0            // [160][264] bf16 (hi 0-127 | lo 128-255 | pad) ; later dump1 f32 [160][72]
#define OFF_B1 84480        // [72][264] bf16 (W1 rows 0-63, w1a=64, w1b=65, 66-71 zero); later dump2 f32 [160][40]
#define OFF_A2 122496       // [160][136] bf16 (hi 0-63 | lo 64-127 | pad)
#define OFF_B2 166016       // [40][136] bf16 (W2 0-31, w2a=32, w2b=33, 34-39 zero)
#define OFF_WL 176896       // [320][13] f32 transposed
#define OFF_CONST 193536    // sc1[5] bi1[5] sc2[5] bi2[5] bl[13]
#define SMEM_BYTES 193792

#define PA1 528             // bytes/row A1,B1
#define PA2 272             // bytes/row A2,B2
#define PD1 72              // f32/row dump1
#define PD2 40              // f32/row dump2

__device__ __forceinline__ uint32_t s2u(const void* p) {
    uint32_t a;
    asm("{ .reg .u64 t; cvta.to.shared.u64 t, %1; cvt.u32.u64 %0, t; }" : "=r"(a) : "l"(p));
    return a;
}
__device__ __forceinline__ void ldm_x4(uint32_t* r, uint32_t a) {
    asm volatile("ldmatrix.sync.aligned.m8n8.x4.shared.b16 {%0,%1,%2,%3},[%4];"
                 : "=r"(r[0]), "=r"(r[1]), "=r"(r[2]), "=r"(r[3]) : "r"(a));
}
__device__ __forceinline__ void ldm_x2(uint32_t* r, uint32_t a) {
    asm volatile("ldmatrix.sync.aligned.m8n8.x2.shared.b16 {%0,%1},[%2];"
                 : "=r"(r[0]), "=r"(r[1]) : "r"(a));
}
__device__ __forceinline__ void mma16816(float* d, const uint32_t* a, const uint32_t* b) {
    asm volatile("mma.sync.aligned.m16n8k16.row.col.f32.bf16.bf16.f32 "
                 "{%0,%1,%2,%3},{%4,%5,%6,%7},{%8,%9},{%0,%1,%2,%3};"
                 : "+f"(d[0]), "+f"(d[1]), "+f"(d[2]), "+f"(d[3])
                 : "r"(a[0]), "r"(a[1]), "r"(a[2]), "r"(a[3]), "r"(b[0]), "r"(b[1]));
}
// bf16 hi/lo split of a float pair -> packed u32s (low half = first element)
__device__ __forceinline__ void split2(float v0, float v1, uint32_t& hip, uint32_t& lop) {
    __nv_bfloat16 h0 = __float2bfloat16(v0), h1 = __float2bfloat16(v1);
    float l0 = v0 - __bfloat162float(h0), l1 = v1 - __bfloat162float(h1);
    __nv_bfloat16 g0 = __float2bfloat16(l0), g1 = __float2bfloat16(l1);
    hip = (uint32_t)__bfloat16_as_ushort(h0) | ((uint32_t)__bfloat16_as_ushort(h1) << 16);
    lop = (uint32_t)__bfloat16_as_ushort(g0) | ((uint32_t)__bfloat16_as_ushort(g1) << 16);
}
__device__ __forceinline__ float wred(float v) {
    #pragma unroll
    for (int s = 16; s > 0; s >>= 1) v += __shfl_xor_sync(0xffffffffu, v, s);
    return v;
}

// e[i][j] = lrelu(s1[i]+s2[j]); softmax over i; o[c][i] += sum_j attn[i][j]*h[c][j]
template <int C>
__device__ __forceinline__ void attn_apply(const float s1[5], const float s2[5],
                                           const float (&h)[C][5], float (&o)[C][5]) {
    #pragma unroll
    for (int j = 0; j < 5; ++j) {
        float e[5]; float m = -1e30f;
        #pragma unroll
        for (int i = 0; i < 5; ++i) {
            float v = s1[i] + s2[j];
            v = v > 0.f ? v : ALPHA * v;
            e[i] = v; m = fmaxf(m, v);
        }
        float Z = 0.f;
        #pragma unroll
        for (int i = 0; i < 5; ++i) { e[i] = __expf(e[i] - m); Z += e[i]; }
        float rz = __fdividef(1.f, Z);
        #pragma unroll
        for (int i = 0; i < 5; ++i) {
            float wv = e[i] * rz;
            #pragma unroll
            for (int c = 0; c < C; ++c) o[c][i] = fmaf(wv, h[c][j], o[c][i]);
        }
    }
}

__global__ void __launch_bounds__(NTHR, 1)
gat_mma_kernel(const float* __restrict__ x,
               const float* __restrict__ Wt1, const float* __restrict__ a11, const float* __restrict__ a21,
               const float* __restrict__ g1, const float* __restrict__ b1,
               const float* __restrict__ m1, const float* __restrict__ v1,
               const float* __restrict__ Wt2, const float* __restrict__ a12, const float* __restrict__ a22,
               const float* __restrict__ g2, const float* __restrict__ b2,
               const float* __restrict__ m2, const float* __restrict__ v2,
               const float* __restrict__ Wl, const float* __restrict__ bl,
               float* __restrict__ out, int B)
{
    extern __shared__ __align__(1024) char smc[];
    const int tid = threadIdx.x;
    const int w = tid >> 5, l = tid & 31;
    const int b0 = blockIdx.x * GROUP;
    const uint32_t smb = s2u(smc);
    float* cst = (float*)(smc + OFF_CONST);

    // ================= staging =================
    // x -> A1 split: rows r = lb*10 + p*5 + n ; 160 rows x 64 k-pairs
    {
        const float* xg = x + (size_t)b0 * 1250;
        for (int i = tid; i < 160 * 64; i += NTHR) {
            int r = i >> 6, kp = i & 63;
            int lb = r / 10, rem = r - lb * 10;
            int p = rem / 5, n = rem - p * 5;
            const float* src = xg + lb * 1250 + n * 250 + p * 125 + 2 * kp;
            float v0 = (2 * kp < 125) ? src[0] : 0.f;
            float v1 = (2 * kp + 1 < 125) ? src[1] : 0.f;
            uint32_t hip, lop; split2(v0, v1, hip, lop);
            *(uint32_t*)(smc + OFF_A1 + r * PA1 + kp * 4) = hip;
            *(uint32_t*)(smc + OFF_A1 + r * PA1 + 256 + kp * 4) = lop;
        }
    }
    // W1 -> B1 rows 0-63
    for (int i = tid; i < 64 * 64; i += NTHR) {
        int o = i >> 6, kp = i & 63;
        float v0 = (2 * kp < 125) ? Wt1[o * 125 + 2 * kp] : 0.f;
        float v1 = (2 * kp + 1 < 125) ? Wt1[o * 125 + 2 * kp + 1] : 0.f;
        uint32_t hip, lop; split2(v0, v1, hip, lop);
        *(uint32_t*)(smc + OFF_B1 + o * PA1 + kp * 4) = hip;
        *(uint32_t*)(smc + OFF_B1 + o * PA1 + 256 + kp * 4) = lop;
    }
    // B1 rows 64 (w1a = W1^T a11), 65 (w1b = W1^T a21)
    if (tid < 128) {
        int k = tid; float sa = 0.f, sb = 0.f;
        if (k < 125) {
            #pragma unroll 4
            for (int o = 0; o < 64; ++o) {
                float wv = Wt1[o * 125 + k];
                sa = fmaf(a11[o], wv, sa); sb = fmaf(a21[o], wv, sb);
            }
        }
        __nv_bfloat16 ha = __float2bfloat16(sa);
        __nv_bfloat16 la = __float2bfloat16(sa - __bfloat162float(ha));
        *(__nv_bfloat16*)(smc + OFF_B1 + 64 * PA1 + k * 2) = ha;
        *(__nv_bfloat16*)(smc + OFF_B1 + 64 * PA1 + 256 + k * 2) = la;
        __nv_bfloat16 hb = __float2bfloat16(sb);
        __nv_bfloat16 lb_ = __float2bfloat16(sb - __bfloat162float(hb));
        *(__nv_bfloat16*)(smc + OFF_B1 + 65 * PA1 + k * 2) = hb;
        *(__nv_bfloat16*)(smc + OFF_B1 + 65 * PA1 + 256 + k * 2) = lb_;
    }
    // B1 rows 66-71 zero
    for (int i = tid; i < 6 * 128; i += NTHR)
        *(uint32_t*)(smc + OFF_B1 + (66 + (i >> 7)) * PA1 + (i & 127) * 4) = 0u;
    // W2 -> B2 rows 0-31
    for (int i = tid; i < 32 * 32; i += NTHR) {
        int o = i >> 5, kp = i & 31;
        uint32_t hip, lop; split2(Wt2[o * 64 + 2 * kp], Wt2[o * 64 + 2 * kp + 1], hip, lop);
        *(uint32_t*)(smc + OFF_B2 + o * PA2 + kp * 4) = hip;
        *(uint32_t*)(smc + OFF_B2 + o * PA2 + 128 + kp * 4) = lop;
    }
    // B2 rows 32 (w2a = W2^T a12), 33 (w2b = W2^T a22)
    if (tid < 64) {
        int k = tid; float sa = 0.f, sb = 0.f;
        #pragma unroll 4
        for (int o = 0; o < 32; ++o) {
            float wv = Wt2[o * 64 + k];
            sa = fmaf(a12[o], wv, sa); sb = fmaf(a22[o], wv, sb);
        }
        __nv_bfloat16 ha = __float2bfloat16(sa);
        __nv_bfloat16 la = __float2bfloat16(sa - __bfloat162float(ha));
        *(__nv_bfloat16*)(smc + OFF_B2 + 32 * PA2 + k * 2) = ha;
        *(__nv_bfloat16*)(smc + OFF_B2 + 32 * PA2 + 128 + k * 2) = la;
        __nv_bfloat16 hb = __float2bfloat16(sb);
        __nv_bfloat16 lb_ = __float2bfloat16(sb - __bfloat162float(hb));
        *(__nv_bfloat16*)(smc + OFF_B2 + 33 * PA2 + k * 2) = hb;
        *(__nv_bfloat16*)(smc + OFF_B2 + 33 * PA2 + 128 + k * 2) = lb_;
    }
    // B2 rows 34-39 zero
    for (int i = tid; i < 6 * 64; i += NTHR)
        *(uint32_t*)(smc + OFF_B2 + (34 + (i >> 6)) * PA2 + (i & 63) * 4) = 0u;
    // Wl transposed
    {
        float* fWL = (float*)(smc + OFF_WL);
        for (int i = tid; i < 4160; i += NTHR) {
            int ii = i / 13, c = i - ii * 13;
            fWL[i] = Wl[c * 320 + ii];
        }
    }
    if (tid < 5) {
        float s = g1[tid] * rsqrtf(v1[tid] + BN_EPS);
        cst[0 + tid] = s; cst[5 + tid] = b1[tid] - m1[tid] * s;
        float s2_ = g2[tid] * rsqrtf(v2[tid] + BN_EPS);
        cst[10 + tid] = s2_; cst[15 + tid] = b2[tid] - m2[tid] * s2_;
    }
    if (tid < 13) cst[20 + tid] = bl[tid];
    __syncthreads();

    // warp tiling: i_m = m-tile pair {i_m, i_m+5}; j_n = n-half
    const int i_m = w % 5, j_n = w / 5;
    const int lrow = l & 15;                 // ldmatrix x4 row
    const int lko  = (l >> 4) * 8;           // ldmatrix x4 k-offset
    const int brow = l & 7;                  // ldmatrix x2 row
    const int bko  = ((l >> 3) & 1) * 8;     // ldmatrix x2 k-offset

    // ================= GEMM1: [160x256] x [72x256] (split 3-pass) =================
    float acc[2][5][4];
    #pragma unroll
    for (int mm = 0; mm < 2; ++mm)
        #pragma unroll
        for (int nt = 0; nt < 5; ++nt)
            #pragma unroll
            for (int q = 0; q < 4; ++q) acc[mm][nt][q] = 0.f;
    {
        const int nbase = j_n * 4;           // 0..4 or 4..8 (tile 4 duplicated)
        #pragma unroll 2
        for (int k8 = 0; k8 < 8; ++k8) {
            int kb = k8 * 16;
            uint32_t Ah[2][4], Al[2][4];
            #pragma unroll
            for (int mm = 0; mm < 2; ++mm) {
                uint32_t ad = smb + OFF_A1 + (uint32_t)(((i_m + 5 * mm) * 16 + lrow) * PA1 + (kb + lko) * 2);
                ldm_x4(Ah[mm], ad);
                ldm_x4(Al[mm], ad + 256);
            }
            #pragma unroll
            for (int nt = 0; nt < 5; ++nt) {
                uint32_t bd = smb + OFF_B1 + (uint32_t)(((nbase + nt) * 8 + brow) * PA1 + (kb + bko) * 2);
                uint32_t Bh[2], Bl[2];
                ldm_x2(Bh, bd); ldm_x2(Bl, bd + 256);
                #pragma unroll
                for (int mm = 0; mm < 2; ++mm) {
                    mma16816(acc[mm][nt], Ah[mm], Bh);
                    mma16816(acc[mm][nt], Al[mm], Bh);
                    mma16816(acc[mm][nt], Ah[mm], Bl);
                }
            }
        }
    }
    __syncthreads();   // A1 reads done -> safe to overwrite as dump1
    // dump D1 -> f32 [160][72]
    {
        float* d1 = (float*)(smc + OFF_A1);
        const int nbase = j_n * 4;
        #pragma unroll
        for (int mm = 0; mm < 2; ++mm) {
            int rb = (i_m + 5 * mm) * 16 + (l >> 2);
            #pragma unroll
            for (int nt = 0; nt < 5; ++nt) {
                int c = (nbase + nt) * 8 + (l & 3) * 2;
                *(float2*)(d1 + rb * PD1 + c)       = make_float2(acc[mm][nt][0], acc[mm][nt][1]);
                *(float2*)(d1 + (rb + 8) * PD1 + c) = make_float2(acc[mm][nt][2], acc[mm][nt][3]);
            }
        }
    }
    __syncthreads();

    // ================= epilogue 1: attn + BN + ReLU + split -> A2 =================
    {
        const float* d1 = (const float*)(smc + OFF_A1);
        for (int u = w; u < 32; u += 10) {
            int lb = u >> 1, p = u & 1;
            int rb = lb * 10 + p * 5;
            float h12[2][5], s1[5], s2[5];
            #pragma unroll
            for (int n = 0; n < 5; ++n) {
                float2 hv = *(const float2*)(d1 + (rb + n) * PD1 + 2 * l);
                h12[0][n] = hv.x; h12[1][n] = hv.y;
                s1[n] = d1[(rb + n) * PD1 + 64];
                s2[n] = d1[(rb + n) * PD1 + 65];
            }
            float o12[2][5];
            #pragma unroll
            for (int n = 0; n < 5; ++n) { o12[0][n] = 0.f; o12[1][n] = 0.f; }
            attn_apply<2>(s1, s2, h12, o12);
            #pragma unroll
            for (int n = 0; n < 5; ++n) {
                float sc = cst[0 + n], bi = cst[5 + n];
                float y0 = fmaxf(fmaf(o12[0][n], sc, bi), 0.f);
                float y1 = fmaxf(fmaf(o12[1][n], sc, bi), 0.f);
                uint32_t hip, lop; split2(y0, y1, hip, lop);
                *(uint32_t*)(smc + OFF_A2 + (rb + n) * PA2 + l * 4) = hip;
                *(uint32_t*)(smc + OFF_A2 + (rb + n) * PA2 + 128 + l * 4) = lop;
            }
        }
    }
    __syncthreads();

    // ================= GEMM2: [160x128] x [40x128] (split 3-pass) =================
    float ac2[2][3][4];
    #pragma unroll
    for (int mm = 0; mm < 2; ++mm)
        #pragma unroll
        for (int nt = 0; nt < 3; ++nt)
            #pragma unroll
            for (int q = 0; q < 4; ++q) ac2[mm][nt][q] = 0.f;
    {
        const int nbase = j_n * 2;           // 0..2 or 2..4 (tile 2 duplicated)
        #pragma unroll
        for (int k8 = 0; k8 < 4; ++k8) {
            int kb = k8 * 16;
            uint32_t Ah[2][4], Al[2][4];
            #pragma unroll
            for (int mm = 0; mm < 2; ++mm) {
                uint32_t ad = smb + OFF_A2 + (uint32_t)(((i_m + 5 * mm) * 16 + lrow) * PA2 + (kb + lko) * 2);
                ldm_x4(Ah[mm], ad);
                ldm_x4(Al[mm], ad + 128);
            }
            #pragma unroll
            for (int nt = 0; nt < 3; ++nt) {
                uint32_t bd = smb + OFF_B2 + (uint32_t)(((nbase + nt) * 8 + brow) * PA2 + (kb + bko) * 2);
                uint32_t Bh[2], Bl[2];
                ldm_x2(Bh, bd); ldm_x2(Bl, bd + 128);
                #pragma unroll
                for (int mm = 0; mm < 2; ++mm) {
                    mma16816(ac2[mm][nt], Ah[mm], Bh);
                    mma16816(ac2[mm][nt], Al[mm], Bh);
                    mma16816(ac2[mm][nt], Ah[mm], Bl);
                }
            }
        }
    }
    __syncthreads();   // B1 reads long done -> dump2 aliases B1
    {
        float* d2 = (float*)(smc + OFF_B1);
        const int nbase = j_n * 2;
        #pragma unroll
        for (int mm = 0; mm < 2; ++mm) {
            int rb = (i_m + 5 * mm) * 16 + (l >> 2);
            #pragma unroll
            for (int nt = 0; nt < 3; ++nt) {
                int c = (nbase + nt) * 8 + (l & 3) * 2;
                *(float2*)(d2 + rb * PD2 + c)       = make_float2(ac2[mm][nt][0], ac2[mm][nt][1]);
                *(float2*)(d2 + (rb + 8) * PD2 + c) = make_float2(ac2[mm][nt][2], ac2[mm][nt][3]);
            }
        }
    }
    __syncthreads();

    // ================= epilogue 2: cross attn + BN + final linear =================
    {
        const float* d2 = (const float*)(smc + OFF_B1);
        const float* fWL = (const float*)(smc + OFF_WL);
        for (int u = w; u < GROUP; u += 10) {
            int rA = u * 10, rN = u * 10 + 5;
            float hA[1][5], hN[1][5];
            float s1a[5], s2a[5], s1b[5], s2b[5];
            #pragma unroll
            for (int n = 0; n < 5; ++n) {
                hA[0][n] = d2[(rA + n) * PD2 + l];
                hN[0][n] = d2[(rN + n) * PD2 + l];
                s1a[n] = d2[(rA + n) * PD2 + 32];   // hA @ a12
                s2a[n] = d2[(rN + n) * PD2 + 33];   // hN @ a22
                s1b[n] = d2[(rN + n) * PD2 + 32];   // hN @ a12
                s2b[n] = d2[(rA + n) * PD2 + 33];   // hA @ a22
            }
            float oA[1][5], oN[1][5];
            #pragma unroll
            for (int n = 0; n < 5; ++n) { oA[0][n] = 0.f; oN[0][n] = 0.f; }
            attn_apply<1>(s1a, s2a, hA, oA);
            attn_apply<1>(s1b, s2b, hN, oN);
            float fa[5], fb[5];
            #pragma unroll
            for (int n = 0; n < 5; ++n) {
                float sc = cst[10 + n], bi = cst[15 + n];
                fa[n] = fmaxf(fmaf(oA[0][n], sc, bi), 0.f);
                fb[n] = fmaxf(fmaf(oN[0][n], sc, bi), 0.f);
            }
            float acc13[13];
            #pragma unroll
            for (int c = 0; c < 13; ++c) acc13[c] = 0.f;
            #pragma unroll
            for (int n = 0; n < 5; ++n) {
                const float* wA = fWL + (n * 64 + l) * 13;
                const float* wB = fWL + (n * 64 + 32 + l) * 13;
                #pragma unroll
                for (int c = 0; c < 13; ++c)
                    acc13[c] += fa[n] * wA[c] + fb[n] * wB[c];
            }
            #pragma unroll
            for (int c = 0; c < 13; ++c) acc13[c] = wred(acc13[c]);
            if (l < 13) {
                float ov = 0.f;
                #pragma unroll
                for (int c = 0; c < 13; ++c) if (l == c) ov = acc13[c];
                out[(size_t)(b0 + u) * 13 + l] = ov + cst[20 + l];
            }
        }
    }
}

extern "C" void kernel_launch(void* const* d_in, const int* in_sizes, int n_in,
                              void* d_out, int out_size)
{
    const float* x   = (const float*)d_in[0];
    const float* Wt1 = (const float*)d_in[1];
    const float* a11 = (const float*)d_in[2];
    const float* a21 = (const float*)d_in[3];
    const float* g1  = (const float*)d_in[4];
    const float* b1  = (const float*)d_in[5];
    const float* m1  = (const float*)d_in[6];
    const float* v1  = (const float*)d_in[7];
    const float* Wt2 = (const float*)d_in[8];
    const float* a12 = (const float*)d_in[9];
    const float* a22 = (const float*)d_in[10];
    const float* g2  = (const float*)d_in[11];
    const float* b2  = (const float*)d_in[12];
    const float* m2  = (const float*)d_in[13];
    const float* v2  = (const float*)d_in[14];
    const float* Wl  = (const float*)d_in[15];
    const float* bl  = (const float*)d_in[16];

    int B = in_sizes[0] / 1250;
    int grid = (B + GROUP - 1) / GROUP;
    cudaFuncSetAttribute(gat_mma_kernel, cudaFuncAttributeMaxDynamicSharedMemorySize, SMEM_BYTES);
    gat_mma_kernel<<<grid, NTHR, SMEM_BYTES>>>(x, Wt1, a11, a21, g1, b1, m1, v1,
                                               Wt2, a12, a22, g2, b2, m2, v2, Wl, bl,
                                               (float*)d_out, B);
}

// round 5
// speedup vs baseline: 3.3305x; 3.3305x over previous
#include <cuda_runtime.h>
#include <cuda_bf16.h>
#include <cstdint>

#define NTHR 320
#define GROUP 8
#define ALPHA 0.2f
#define BN_EPS 1e-5f

#define PA1 528           // bytes/row A1 (hi 0..255 | lo 256..511 | pad)
#define PA2 272           // bytes/row A2 (hi 0..127 | lo 128..255 | pad)
#define PD1 72            // f32/row dump1
#define PD2 40            // f32/row dump2
#define OFF_A1 0          // 80*528 = 42240 ; dump1 [80][72]f32 / dump2 [80][40]f32 alias here
#define OFF_A2 42240      // 80*272 = 21760
#define SMEM_BYTES 64064

// ---- device-global prepared weights ----
__device__ uint4  g_W1F[2304];   // [9 ntile][8 k8][32 lane] B-frag {Bh0,Bh1,Bl0,Bl1}
__device__ uint4  g_W2F[640];    // [5][4][32]
__device__ float2 g_WLP[2080];   // [13 c][5 n][32 l] = (Wl[c][n*64+l], Wl[c][n*64+32+l])
__device__ float  g_SCORE[512];  // w1a[0..127] w1b[128..255] w2a[256..319] w2b[384..447]
__device__ float  g_CST[64];     // sc1@0 bi1@8 sc2@16 bi2@24 bl@32

// ------------- helpers -------------
__device__ __forceinline__ uint32_t s2u(const void* p) {
    uint32_t a;
    asm("{ .reg .u64 t; cvta.to.shared.u64 t, %1; cvt.u32.u64 %0, t; }" : "=r"(a) : "l"(p));
    return a;
}
__device__ __forceinline__ void ldm_x4(uint32_t* r, uint32_t a) {
    asm volatile("ldmatrix.sync.aligned.m8n8.x4.shared.b16 {%0,%1,%2,%3},[%4];"
                 : "=r"(r[0]), "=r"(r[1]), "=r"(r[2]), "=r"(r[3]) : "r"(a));
}
__device__ __forceinline__ void mma16816(float* d, const uint32_t* a, const uint32_t* b) {
    asm volatile("mma.sync.aligned.m16n8k16.row.col.f32.bf16.bf16.f32 "
                 "{%0,%1,%2,%3},{%4,%5,%6,%7},{%8,%9},{%0,%1,%2,%3};"
                 : "+f"(d[0]), "+f"(d[1]), "+f"(d[2]), "+f"(d[3])
                 : "r"(a[0]), "r"(a[1]), "r"(a[2]), "r"(a[3]), "r"(b[0]), "r"(b[1]));
}
// cheap truncation hi/lo split of a float pair -> packed bf16x2 (low half = first elem)
__device__ __forceinline__ void csplit2(float v0, float v1, uint32_t& hip, uint32_t& lop) {
    uint32_t u0 = __float_as_uint(v0), u1 = __float_as_uint(v1);
    hip = __byte_perm(u0, u1, 0x7632);
    float l0 = v0 - __uint_as_float(u0 & 0xffff0000u);
    float l1 = v1 - __uint_as_float(u1 & 0xffff0000u);
    asm("cvt.rn.bf16x2.f32 %0, %1, %2;" : "=r"(lop) : "f"(l1), "f"(l0));
}
// accurate split (prologue only)
__device__ __forceinline__ void asplit(float v, uint16_t& h, uint16_t& lo) {
    __nv_bfloat16 hh = __float2bfloat16(v);
    __nv_bfloat16 ll = __float2bfloat16(v - __bfloat162float(hh));
    h = __bfloat16_as_ushort(hh); lo = __bfloat16_as_ushort(ll);
}
__device__ __forceinline__ float wred(float v) {
    #pragma unroll
    for (int s = 16; s > 0; s >>= 1) v += __shfl_xor_sync(0xffffffffu, v, s);
    return v;
}
template <int C>
__device__ __forceinline__ void attn_apply(const float s1[5], const float s2[5],
                                           const float (&h)[C][5], float (&o)[C][5]) {
    #pragma unroll
    for (int j = 0; j < 5; ++j) {
        float e[5]; float m = -1e30f;
        #pragma unroll
        for (int i = 0; i < 5; ++i) {
            float v = s1[i] + s2[j];
            v = v > 0.f ? v : ALPHA * v;
            e[i] = v; m = fmaxf(m, v);
        }
        float Z = 0.f;
        #pragma unroll
        for (int i = 0; i < 5; ++i) { e[i] = __expf(e[i] - m); Z += e[i]; }
        float rz = __fdividef(1.f, Z);
        #pragma unroll
        for (int i = 0; i < 5; ++i) {
            float wv = e[i] * rz;
            #pragma unroll
            for (int c = 0; c < C; ++c) o[c][i] = fmaf(wv, h[c][j], o[c][i]);
        }
    }
}

template<int NT, int NB, int NK8, int LOOFF>
__device__ __forceinline__ void run_gemm(float (&acc)[NT][4], const uint4* __restrict__ WF,
                                         uint32_t abase, int l) {
    #pragma unroll
    for (int t = 0; t < NT; ++t) { acc[t][0]=0.f; acc[t][1]=0.f; acc[t][2]=0.f; acc[t][3]=0.f; }
    #pragma unroll
    for (int k8 = 0; k8 < NK8; ++k8) {
        uint32_t Ah[4], Al[4];
        uint32_t ad = abase + k8 * 32;
        ldm_x4(Ah, ad); ldm_x4(Al, ad + LOOFF);
        #pragma unroll
        for (int t = 0; t < NT; ++t) {
            uint4 bf = WF[((NB + t) * NK8 + k8) * 32 + l];
            uint32_t Bh[2] = {bf.x, bf.y};
            uint32_t Bl[2] = {bf.z, bf.w};
            mma16816(acc[t], Ah, Bh);
            mma16816(acc[t], Al, Bh);
            mma16816(acc[t], Ah, Bl);
        }
    }
}
template<int NT, int NB>
__device__ __forceinline__ void dump_acc(const float (&acc)[NT][4], float* d, int pitch, int i_m, int l) {
    int rb = i_m * 16 + (l >> 2);
    #pragma unroll
    for (int t = 0; t < NT; ++t) {
        int c = (NB + t) * 8 + (l & 3) * 2;
        *(float2*)(d + rb * pitch + c)       = make_float2(acc[t][0], acc[t][1]);
        *(float2*)(d + (rb + 8) * pitch + c) = make_float2(acc[t][2], acc[t][3]);
    }
}

// ================= prologue 1: score vectors, consts, Wl repack =================
__global__ void prep1(const float* __restrict__ Wt1, const float* __restrict__ a11, const float* __restrict__ a21,
                      const float* __restrict__ Wt2, const float* __restrict__ a12, const float* __restrict__ a22,
                      const float* __restrict__ Wl, const float* __restrict__ bl,
                      const float* __restrict__ g1, const float* __restrict__ b1,
                      const float* __restrict__ m1, const float* __restrict__ v1,
                      const float* __restrict__ g2, const float* __restrict__ b2,
                      const float* __restrict__ m2, const float* __restrict__ v2)
{
    int t = blockIdx.x * blockDim.x + threadIdx.x;
    if (t < 128) {
        float sa = 0.f, sb = 0.f;
        if (t < 125) {
            #pragma unroll 4
            for (int o = 0; o < 64; ++o) {
                float wv = Wt1[o * 125 + t];
                sa = fmaf(a11[o], wv, sa); sb = fmaf(a21[o], wv, sb);
            }
        }
        g_SCORE[t] = sa; g_SCORE[128 + t] = sb;
    } else if (t < 192) {
        int k = t - 128;
        float sa = 0.f, sb = 0.f;
        #pragma unroll 4
        for (int o = 0; o < 32; ++o) {
            float wv = Wt2[o * 64 + k];
            sa = fmaf(a12[o], wv, sa); sb = fmaf(a22[o], wv, sb);
        }
        g_SCORE[256 + k] = sa; g_SCORE[384 + k] = sb;
    } else if (t >= 200 && t < 205) {
        int i = t - 200;
        float s = g1[i] * rsqrtf(v1[i] + BN_EPS);
        g_CST[i] = s; g_CST[8 + i] = b1[i] - m1[i] * s;
    } else if (t >= 205 && t < 210) {
        int i = t - 205;
        float s = g2[i] * rsqrtf(v2[i] + BN_EPS);
        g_CST[16 + i] = s; g_CST[24 + i] = b2[i] - m2[i] * s;
    } else if (t >= 210 && t < 223) {
        g_CST[32 + (t - 210)] = bl[t - 210];
    }
    int e = t - 256;
    if (e >= 0 && e < 2080) {
        int c = e / 160, rem = e - c * 160;
        int n = rem >> 5, l = rem & 31;
        g_WLP[e] = make_float2(Wl[c * 320 + n * 64 + l], Wl[c * 320 + n * 64 + 32 + l]);
    }
}

// ================= prologue 2: W fragments (needs g_SCORE) =================
__global__ void prep2(const float* __restrict__ Wt1, const float* __restrict__ Wt2)
{
    int e = blockIdx.x * blockDim.x + threadIdx.x;
    if (e < 2304) {
        int T = e >> 8, k8 = (e >> 5) & 7, L = e & 31;
        int n = T * 8 + (L >> 2);
        int k0 = k8 * 16 + 2 * (L & 3);
        float v[4];
        #pragma unroll
        for (int q = 0; q < 4; ++q) {
            int k = k0 + (q >> 1) * 8 + (q & 1);
            float vv = 0.f;
            if (n < 64)      vv = (k < 125) ? Wt1[n * 125 + k] : 0.f;
            else if (n == 64) vv = g_SCORE[k];
            else if (n == 65) vv = g_SCORE[128 + k];
            v[q] = vv;
        }
        uint16_t h[4], lo[4];
        #pragma unroll
        for (int q = 0; q < 4; ++q) asplit(v[q], h[q], lo[q]);
        g_W1F[e] = make_uint4((uint32_t)h[0] | ((uint32_t)h[1] << 16),
                              (uint32_t)h[2] | ((uint32_t)h[3] << 16),
                              (uint32_t)lo[0] | ((uint32_t)lo[1] << 16),
                              (uint32_t)lo[2] | ((uint32_t)lo[3] << 16));
    } else if (e < 2944) {
        int f = e - 2304;
        int T = f >> 7, k8 = (f >> 5) & 3, L = f & 31;
        int n = T * 8 + (L >> 2);
        int k0 = k8 * 16 + 2 * (L & 3);
        float v[4];
        #pragma unroll
        for (int q = 0; q < 4; ++q) {
            int k = k0 + (q >> 1) * 8 + (q & 1);
            float vv = 0.f;
            if (n < 32)      vv = Wt2[n * 64 + k];
            else if (n == 32) vv = g_SCORE[256 + k];
            else if (n == 33) vv = g_SCORE[384 + k];
            v[q] = vv;
        }
        uint16_t h[4], lo[4];
        #pragma unroll
        for (int q = 0; q < 4; ++q) asplit(v[q], h[q], lo[q]);
        g_W2F[f] = make_uint4((uint32_t)h[0] | ((uint32_t)h[1] << 16),
                              (uint32_t)h[2] | ((uint32_t)h[3] << 16),
                              (uint32_t)lo[0] | ((uint32_t)lo[1] << 16),
                              (uint32_t)lo[2] | ((uint32_t)lo[3] << 16));
    }
}

// ================= main fused kernel =================
__global__ void __launch_bounds__(NTHR, 2)
gat5_kernel(const float* __restrict__ x, float* __restrict__ out, int B)
{
    extern __shared__ __align__(16) char smc[];
    const int tid = threadIdx.x;
    const int w = tid >> 5, l = tid & 31;
    const int b0 = blockIdx.x * GROUP;
    const uint32_t smb = s2u(smc);

    // ---- stage x -> A1 (cheap split). Warp-fixed (p,n): rows r = j*10 + w ----
    {
        const int pp = w / 5, nn = w - 5 * pp;
        const float* xrow = x + (size_t)b0 * 1250 + nn * 250 + pp * 125;
        #pragma unroll
        for (int j = 0; j < GROUP; ++j) {
            const float* src = xrow + (size_t)j * 1250;
            bool bv = (b0 + j) < B;
            char* arow = smc + OFF_A1 + (j * 10 + w) * PA1;
            float v0 = bv ? src[2 * l] : 0.f;
            float v1 = bv ? src[2 * l + 1] : 0.f;
            uint32_t hip, lop; csplit2(v0, v1, hip, lop);
            *(uint32_t*)(arow + l * 4) = hip;
            *(uint32_t*)(arow + 256 + l * 4) = lop;
            int k = 64 + 2 * l;
            float u0 = (bv && k < 125) ? src[k] : 0.f;
            float u1 = (bv && k + 1 < 125) ? src[k + 1] : 0.f;
            csplit2(u0, u1, hip, lop);
            *(uint32_t*)(arow + (l + 32) * 4) = hip;
            *(uint32_t*)(arow + 256 + (l + 32) * 4) = lop;
        }
    }
    __syncthreads();

    const int i_m = w % 5, j_n = w / 5;
    float* d1 = (float*)smc;   // dump region aliases A1

    // ---- GEMM1: A[80x(128hi|128lo)] x W1frag -> dump1 [80][72] ----
    {
        uint32_t abase = smb + OFF_A1 + (uint32_t)((i_m * 16 + (l & 15)) * PA1 + ((l >> 4) * 8) * 2);
        if (j_n == 0) {
            float acc[5][4];
            run_gemm<5, 0, 8, 256>(acc, g_W1F, abase, l);
            __syncthreads();
            dump_acc<5, 0>(acc, d1, PD1, i_m, l);
        } else {
            float acc[4][4];
            run_gemm<4, 5, 8, 256>(acc, g_W1F, abase, l);
            __syncthreads();
            dump_acc<4, 5>(acc, d1, PD1, i_m, l);
        }
    }
    __syncthreads();

    // ---- epilogue 1: attention + BN + ReLU + split -> A2 ----
    {
        float sc1[5], bi1[5];
        #pragma unroll
        for (int n = 0; n < 5; ++n) { sc1[n] = g_CST[n]; bi1[n] = g_CST[8 + n]; }
        for (int u = w; u < 2 * GROUP; u += 10) {
            int lb = u >> 1, p = u & 1;
            int rb = lb * 10 + p * 5;
            float h12[2][5], s1[5], s2[5];
            #pragma unroll
            for (int n = 0; n < 5; ++n) {
                float2 hv = *(const float2*)(d1 + (rb + n) * PD1 + 2 * l);
                h12[0][n] = hv.x; h12[1][n] = hv.y;
                float2 sv = *(const float2*)(d1 + (rb + n) * PD1 + 64);
                s1[n] = sv.x; s2[n] = sv.y;
            }
            float o12[2][5];
            #pragma unroll
            for (int n = 0; n < 5; ++n) { o12[0][n] = 0.f; o12[1][n] = 0.f; }
            attn_apply<2>(s1, s2, h12, o12);
            #pragma unroll
            for (int n = 0; n < 5; ++n) {
                float y0 = fmaxf(fmaf(o12[0][n], sc1[n], bi1[n]), 0.f);
                float y1 = fmaxf(fmaf(o12[1][n], sc1[n], bi1[n]), 0.f);
                uint32_t hip, lop; csplit2(y0, y1, hip, lop);
                char* arow = smc + OFF_A2 + (rb + n) * PA2;
                *(uint32_t*)(arow + l * 4) = hip;
                *(uint32_t*)(arow + 128 + l * 4) = lop;
            }
        }
    }
    __syncthreads();

    // ---- GEMM2: A2[80x(64hi|64lo)] x W2frag -> dump2 [80][40] ----
    {
        uint32_t abase = smb + OFF_A2 + (uint32_t)((i_m * 16 + (l & 15)) * PA2 + ((l >> 4) * 8) * 2);
        if (j_n == 0) {
            float acc[3][4];
            run_gemm<3, 0, 4, 128>(acc, g_W2F, abase, l);
            __syncthreads();
            dump_acc<3, 0>(acc, d1, PD2, i_m, l);
        } else {
            float acc[2][4];
            run_gemm<2, 3, 4, 128>(acc, g_W2F, abase, l);
            __syncthreads();
            dump_acc<2, 3>(acc, d1, PD2, i_m, l);
        }
    }
    __syncthreads();

    // ---- epilogue 2: cross attention + BN + final linear ----
    if (w < GROUP) {
        const int u = w;
        int bb = b0 + u;
        float sc2v[5], bi2v[5];
        #pragma unroll
        for (int n = 0; n < 5; ++n) { sc2v[n] = g_CST[16 + n]; bi2v[n] = g_CST[24 + n]; }
        int rA = u * 10, rN = rA + 5;
        float hA[1][5], hN[1][5];
        float s1a[5], s2a[5], s1b[5], s2b[5];
        #pragma unroll
        for (int n = 0; n < 5; ++n) {
            hA[0][n] = d1[(rA + n) * PD2 + l];
            hN[0][n] = d1[(rN + n) * PD2 + l];
            float2 sA = *(const float2*)(d1 + (rA + n) * PD2 + 32);  // (hA@a12, hA@a22)
            float2 sN = *(const float2*)(d1 + (rN + n) * PD2 + 32);  // (hN@a12, hN@a22)
            s1a[n] = sA.x; s2b[n] = sA.y;
            s1b[n] = sN.x; s2a[n] = sN.y;
        }
        float oA[1][5], oN[1][5];
        #pragma unroll
        for (int n = 0; n < 5; ++n) { oA[0][n] = 0.f; oN[0][n] = 0.f; }
        attn_apply<1>(s1a, s2a, hA, oA);
        attn_apply<1>(s1b, s2b, hN, oN);
        float fa[5], fb[5];
        #pragma unroll
        for (int n = 0; n < 5; ++n) {
            fa[n] = fmaxf(fmaf(oA[0][n], sc2v[n], bi2v[n]), 0.f);
            fb[n] = fmaxf(fmaf(oN[0][n], sc2v[n], bi2v[n]), 0.f);
        }
        float acc13[13];
        #pragma unroll
        for (int c = 0; c < 13; ++c) acc13[c] = 0.f;
        #pragma unroll
        for (int n = 0; n < 5; ++n) {
            #pragma unroll
            for (int c = 0; c < 13; ++c) {
                float2 wp = g_WLP[(c * 5 + n) * 32 + l];
                acc13[c] += fa[n] * wp.x + fb[n] * wp.y;
            }
        }
        #pragma unroll
        for (int c = 0; c < 13; ++c) acc13[c] = wred(acc13[c]);
        if (l < 13 && bb < B) {
            float ov = 0.f;
            #pragma unroll
            for (int c = 0; c < 13; ++c) if (l == c) ov = acc13[c];
            out[(size_t)bb * 13 + l] = ov + g_CST[32 + l];
        }
    }
}

extern "C" void kernel_launch(void* const* d_in, const int* in_sizes, int n_in,
                              void* d_out, int out_size)
{
    const float* x   = (const float*)d_in[0];
    const float* Wt1 = (const float*)d_in[1];
    const float* a11 = (const float*)d_in[2];
    const float* a21 = (const float*)d_in[3];
    const float* g1  = (const float*)d_in[4];
    const float* b1  = (const float*)d_in[5];
    const float* m1  = (const float*)d_in[6];
    const float* v1  = (const float*)d_in[7];
    const float* Wt2 = (const float*)d_in[8];
    const float* a12 = (const float*)d_in[9];
    const float* a22 = (const float*)d_in[10];
    const float* g2  = (const float*)d_in[11];
    const float* b2  = (const float*)d_in[12];
    const float* m2  = (const float*)d_in[13];
    const float* v2  = (const float*)d_in[14];
    const float* Wl  = (const float*)d_in[15];
    const float* bl  = (const float*)d_in[16];

    int B = in_sizes[0] / 1250;
    prep1<<<10, 256>>>(Wt1, a11, a21, Wt2, a12, a22, Wl, bl,
                       g1, b1, m1, v1, g2, b2, m2, v2);
    prep2<<<12, 256>>>(Wt1, Wt2);
    int grid = (B + GROUP - 1) / GROUP;
    cudaFuncSetAttribute(gat5_kernel, cudaFuncAttributeMaxDynamicSharedMemorySize, SMEM_BYTES);
    gat5_kernel<<<grid, NTHR, SMEM_BYTES>>>(x, (float*)d_out, B);
}

// round 6
// speedup vs baseline: 3.7537x; 1.1271x over previous
#include <cuda_runtime.h>
#include <cuda_bf16.h>
#include <cstdint>

#define NTHR 320
#define GROUP 8
#define ALPHA 0.2f
#define BN_EPS 1e-5f

// ---- smem layout (bytes) ----
// region0: A1 [80 rows][132 f32 pitch] = 42240 ; dump1 [80][72]f32 = 23040 alias ; dump2 [80][40] alias
// region1: A2 [80][68 f32 pitch] = 21760
#define OFF_A1 0
#define OFF_A2 42240
#define SMEM_BYTES 64064
#define PITCH1 132        // f32 words per A1 row
#define PITCH2 68         // f32 words per A2 row
#define PD1 72
#define PD2 40

// ---- device-global prepared weights (tf32 bit patterns) ----
__device__ uint4  g_W1F[2304];   // [9 ntile][8 q(k16)][32 lane] {b0e,b1e,b0o,b1o}
__device__ uint4  g_W2F[640];    // [5][4][32]
__device__ float2 g_WLP[2080];   // [13 c][5 n][32 l]
__device__ float  g_CST[64];     // sc1@0 bi1@8 sc2@16 bi2@24 bl@32

// ------------- helpers -------------
__device__ __forceinline__ uint32_t f2tf32(float v) {
    uint32_t r; asm("cvt.rna.tf32.f32 %0, %1;" : "=r"(r) : "f"(v)); return r;
}
__device__ __forceinline__ void mma_tf32(float* d, const uint32_t* a, uint32_t b0, uint32_t b1) {
    asm volatile("mma.sync.aligned.m16n8k8.row.col.f32.tf32.tf32.f32 "
                 "{%0,%1,%2,%3},{%4,%5,%6,%7},{%8,%9},{%0,%1,%2,%3};"
                 : "+f"(d[0]), "+f"(d[1]), "+f"(d[2]), "+f"(d[3])
                 : "r"(a[0]), "r"(a[1]), "r"(a[2]), "r"(a[3]), "r"(b0), "r"(b1));
}
__device__ __forceinline__ float wred(float v) {
    #pragma unroll
    for (int s = 16; s > 0; s >>= 1) v += __shfl_xor_sync(0xffffffffu, v, s);
    return v;
}
template <int C>
__device__ __forceinline__ void attn_apply(const float s1[5], const float s2[5],
                                           const float (&h)[C][5], float (&o)[C][5]) {
    #pragma unroll
    for (int j = 0; j < 5; ++j) {
        float e[5]; float m = -1e30f;
        #pragma unroll
        for (int i = 0; i < 5; ++i) {
            float v = s1[i] + s2[j];
            v = v > 0.f ? v : ALPHA * v;
            e[i] = v; m = fmaxf(m, v);
        }
        float Z = 0.f;
        #pragma unroll
        for (int i = 0; i < 5; ++i) { e[i] = __expf(e[i] - m); Z += e[i]; }
        float rz = __fdividef(1.f, Z);
        #pragma unroll
        for (int i = 0; i < 5; ++i) {
            float wv = e[i] * rz;
            #pragma unroll
            for (int c = 0; c < C; ++c) o[c][i] = fmaf(wv, h[c][j], o[c][i]);
        }
    }
}

// tf32 GEMM: A from smem rows (conflict-free LDS.32), B frags from global (L1-hot)
template<int NT, int NB, int NQ>
__device__ __forceinline__ void run_gemm(float (&acc)[NT][4], const uint4* __restrict__ WF,
                                         const float* __restrict__ p0, const float* __restrict__ p1,
                                         int l) {
    #pragma unroll
    for (int t = 0; t < NT; ++t) { acc[t][0]=0.f; acc[t][1]=0.f; acc[t][2]=0.f; acc[t][3]=0.f; }
    #pragma unroll
    for (int q = 0; q < NQ; ++q) {
        const int k0 = 16 * q;
        uint32_t aE[4], aO[4];
        aE[0] = __float_as_uint(p0[k0]);      aE[1] = __float_as_uint(p1[k0]);
        aE[2] = __float_as_uint(p0[k0 + 4]);  aE[3] = __float_as_uint(p1[k0 + 4]);
        aO[0] = __float_as_uint(p0[k0 + 8]);  aO[1] = __float_as_uint(p1[k0 + 8]);
        aO[2] = __float_as_uint(p0[k0 + 12]); aO[3] = __float_as_uint(p1[k0 + 12]);
        #pragma unroll
        for (int t = 0; t < NT; ++t) {
            uint4 bf = WF[((NB + t) * NQ + q) * 32 + l];
            mma_tf32(acc[t], aE, bf.x, bf.y);
            mma_tf32(acc[t], aO, bf.z, bf.w);
        }
    }
}
template<int NT, int NB>
__device__ __forceinline__ void dump_acc(const float (&acc)[NT][4], float* d, int pitch, int i_m, int l) {
    int rb = i_m * 16 + (l >> 2);
    #pragma unroll
    for (int t = 0; t < NT; ++t) {
        int c = (NB + t) * 8 + (l & 3) * 2;
        *(float2*)(d + rb * pitch + c)       = make_float2(acc[t][0], acc[t][1]);
        *(float2*)(d + (rb + 8) * pitch + c) = make_float2(acc[t][2], acc[t][3]);
    }
}

// ================= single merged prep kernel (1 block, 1024 threads) =================
__global__ void __launch_bounds__(1024, 1)
prep(const float* __restrict__ Wt1, const float* __restrict__ a11, const float* __restrict__ a21,
     const float* __restrict__ Wt2, const float* __restrict__ a12, const float* __restrict__ a22,
     const float* __restrict__ Wl, const float* __restrict__ bl,
     const float* __restrict__ g1, const float* __restrict__ b1,
     const float* __restrict__ m1, const float* __restrict__ v1,
     const float* __restrict__ g2, const float* __restrict__ b2,
     const float* __restrict__ m2, const float* __restrict__ v2)
{
    __shared__ float s_score[512];   // w1a[0..127] w1b[128..255] w2a[256..319] w2b[384..447]
    const int t = threadIdx.x;

    // scores, 4-thread parallel reduction per k
    if (t < 512) {
        int k = t >> 2, s = t & 3;
        float sa = 0.f, sb = 0.f;
        if (k < 125) {
            #pragma unroll 4
            for (int oo = 0; oo < 16; ++oo) {
                int o = s * 16 + oo;
                float wv = Wt1[o * 125 + k];
                sa = fmaf(a11[o], wv, sa); sb = fmaf(a21[o], wv, sb);
            }
        }
        sa += __shfl_xor_sync(0xffffffffu, sa, 1); sa += __shfl_xor_sync(0xffffffffu, sa, 2);
        sb += __shfl_xor_sync(0xffffffffu, sb, 1); sb += __shfl_xor_sync(0xffffffffu, sb, 2);
        if (s == 0) { s_score[k] = sa; s_score[128 + k] = sb; }
    } else if (t < 768) {
        int k = (t - 512) >> 2, s = t & 3;
        float sa = 0.f, sb = 0.f;
        #pragma unroll
        for (int oo = 0; oo < 8; ++oo) {
            int o = s * 8 + oo;
            float wv = Wt2[o * 64 + k];
            sa = fmaf(a12[o], wv, sa); sb = fmaf(a22[o], wv, sb);
        }
        sa += __shfl_xor_sync(0xffffffffu, sa, 1); sa += __shfl_xor_sync(0xffffffffu, sa, 2);
        sb += __shfl_xor_sync(0xffffffffu, sb, 1); sb += __shfl_xor_sync(0xffffffffu, sb, 2);
        if (s == 0) { s_score[256 + k] = sa; s_score[384 + k] = sb; }
    } else if (t >= 800 && t < 805) {
        int i = t - 800;
        float s = g1[i] * rsqrtf(v1[i] + BN_EPS);
        g_CST[i] = s; g_CST[8 + i] = b1[i] - m1[i] * s;
    } else if (t >= 805 && t < 810) {
        int i = t - 805;
        float s = g2[i] * rsqrtf(v2[i] + BN_EPS);
        g_CST[16 + i] = s; g_CST[24 + i] = b2[i] - m2[i] * s;
    } else if (t >= 810 && t < 823) {
        g_CST[32 + (t - 810)] = bl[t - 810];
    }
    for (int e = t; e < 2080; e += 1024) {
        int c = e / 160, rem = e - c * 160;
        int n = rem >> 5, l = rem & 31;
        g_WLP[e] = make_float2(Wl[c * 320 + n * 64 + l], Wl[c * 320 + n * 64 + 32 + l]);
    }
    __syncthreads();

    // W1 fragments
    for (int e = t; e < 2304; e += 1024) {
        int T = e >> 8, q = (e >> 5) & 7, L = e & 31;
        int g = L >> 2, tt = L & 3;
        int nn = T * 8 + g;
        uint32_t v[4];
        #pragma unroll
        for (int i = 0; i < 4; ++i) {
            int k = 16 * q + (i >> 1) * 8 + (i & 1) * 4 + tt;
            float vv = 0.f;
            if (k < 125) {
                if (nn < 64)      vv = Wt1[nn * 125 + k];
                else if (nn == 64) vv = s_score[k];
                else if (nn == 65) vv = s_score[128 + k];
            }
            v[i] = f2tf32(vv);
        }
        g_W1F[e] = make_uint4(v[0], v[1], v[2], v[3]);
    }
    // W2 fragments
    for (int f = t; f < 640; f += 1024) {
        int T = f >> 7, q = (f >> 5) & 3, L = f & 31;
        int g = L >> 2, tt = L & 3;
        int nn = T * 8 + g;
        uint32_t v[4];
        #pragma unroll
        for (int i = 0; i < 4; ++i) {
            int k = 16 * q + (i >> 1) * 8 + (i & 1) * 4 + tt;
            float vv = 0.f;
            if (nn < 32)      vv = Wt2[nn * 64 + k];
            else if (nn == 32) vv = s_score[256 + k];
            else if (nn == 33) vv = s_score[384 + k];
            v[i] = f2tf32(vv);
        }
        g_W2F[f] = make_uint4(v[0], v[1], v[2], v[3]);
    }
}

// ================= main fused kernel =================
__global__ void __launch_bounds__(NTHR, 3)
gat6_kernel(const float* __restrict__ x, float* __restrict__ out, int B)
{
    extern __shared__ __align__(16) char smc[];
    const int tid = threadIdx.x;
    const int w = tid >> 5, l = tid & 31;
    const int b0 = blockIdx.x * GROUP;
    float* A1 = (float*)(smc + OFF_A1);
    float* A2 = (float*)(smc + OFF_A2);

    // ---- stage x -> A1 rows (tf32, row-major pitch 132, conflict-free) ----
    {
        const int pp = w / 5, nn = w - 5 * pp;   // row within batch = w
        const float* xrow = x + (size_t)b0 * 1250 + nn * 250 + pp * 125;
        #pragma unroll
        for (int j = 0; j < GROUP; ++j) {
            const float* src = xrow + (size_t)j * 1250;
            bool bv = (b0 + j) < B;
            float* arow = A1 + (j * 10 + w) * PITCH1;
            #pragma unroll
            for (int i = 0; i < 4; ++i) {
                int k = l + 32 * i;
                float v = (bv && k < 125) ? src[k] : 0.f;
                *(uint32_t*)(arow + k) = f2tf32(v);
            }
        }
    }
    __syncthreads();

    const int i_m = w % 5, j_n = w / 5;
    const int g = l >> 2, tt = l & 3;
    float* d1 = A1;                      // dump region aliases A1

    // ---- GEMM1: A[80x128] x W1frag[72x128] -> dump1 [80][72] ----
    {
        const float* p0 = A1 + (i_m * 16 + g) * PITCH1 + tt;
        const float* p1 = p0 + 8 * PITCH1;
        if (j_n == 0) {
            float acc[5][4];
            run_gemm<5, 0, 8>(acc, g_W1F, p0, p1, l);
            __syncthreads();
            dump_acc<5, 0>(acc, d1, PD1, i_m, l);
        } else {
            float acc[4][4];
            run_gemm<4, 5, 8>(acc, g_W1F, p0, p1, l);
            __syncthreads();
            dump_acc<4, 5>(acc, d1, PD1, i_m, l);
        }
    }
    __syncthreads();

    // ---- epilogue 1: attention + BN + ReLU -> A2 (tf32 rows) ----
    {
        float sc1[5], bi1[5];
        #pragma unroll
        for (int n = 0; n < 5; ++n) { sc1[n] = g_CST[n]; bi1[n] = g_CST[8 + n]; }
        for (int u = w; u < 2 * GROUP; u += 10) {
            int lb = u >> 1, p = u & 1;
            int rb = lb * 10 + p * 5;
            float h12[2][5], s1[5], s2[5];
            #pragma unroll
            for (int n = 0; n < 5; ++n) {
                float2 hv = *(const float2*)(d1 + (rb + n) * PD1 + 2 * l);
                h12[0][n] = hv.x; h12[1][n] = hv.y;
                float2 sv = *(const float2*)(d1 + (rb + n) * PD1 + 64);
                s1[n] = sv.x; s2[n] = sv.y;
            }
            float o12[2][5];
            #pragma unroll
            for (int n = 0; n < 5; ++n) { o12[0][n] = 0.f; o12[1][n] = 0.f; }
            attn_apply<2>(s1, s2, h12, o12);
            #pragma unroll
            for (int n = 0; n < 5; ++n) {
                float y0 = fmaxf(fmaf(o12[0][n], sc1[n], bi1[n]), 0.f);
                float y1 = fmaxf(fmaf(o12[1][n], sc1[n], bi1[n]), 0.f);
                uint2 pk = make_uint2(f2tf32(y0), f2tf32(y1));
                *(uint2*)(A2 + (rb + n) * PITCH2 + 2 * l) = pk;
            }
        }
    }
    __syncthreads();

    // ---- GEMM2: A2[80x64] x W2frag[40x64] -> dump2 [80][40] (region0, no extra sync) ----
    float* d2 = A1;
    {
        const float* p0 = A2 + (i_m * 16 + g) * PITCH2 + tt;
        const float* p1 = p0 + 8 * PITCH2;
        if (j_n == 0) {
            float acc[3][4];
            run_gemm<3, 0, 4>(acc, g_W2F, p0, p1, l);
            dump_acc<3, 0>(acc, d2, PD2, i_m, l);
        } else {
            float acc[2][4];
            run_gemm<2, 3, 4>(acc, g_W2F, p0, p1, l);
            dump_acc<2, 3>(acc, d2, PD2, i_m, l);
        }
    }
    __syncthreads();

    // ---- epilogue 2: cross attention + BN + final linear ----
    if (w < GROUP) {
        const int u = w;
        int bb = b0 + u;
        float sc2v[5], bi2v[5];
        #pragma unroll
        for (int n = 0; n < 5; ++n) { sc2v[n] = g_CST[16 + n]; bi2v[n] = g_CST[24 + n]; }
        int rA = u * 10, rN = rA + 5;
        float hA[1][5], hN[1][5];
        float s1a[5], s2a[5], s1b[5], s2b[5];
        #pragma unroll
        for (int n = 0; n < 5; ++n) {
            hA[0][n] = d2[(rA + n) * PD2 + l];
            hN[0][n] = d2[(rN + n) * PD2 + l];
            float2 sA = *(const float2*)(d2 + (rA + n) * PD2 + 32);  // (hA@a12, hA@a22)
            float2 sN = *(const float2*)(d2 + (rN + n) * PD2 + 32);  // (hN@a12, hN@a22)
            s1a[n] = sA.x; s2b[n] = sA.y;
            s1b[n] = sN.x; s2a[n] = sN.y;
        }
        float oA[1][5], oN[1][5];
        #pragma unroll
        for (int n = 0; n < 5; ++n) { oA[0][n] = 0.f; oN[0][n] = 0.f; }
        attn_apply<1>(s1a, s2a, hA, oA);
        attn_apply<1>(s1b, s2b, hN, oN);
        float fa[5], fb[5];
        #pragma unroll
        for (int n = 0; n < 5; ++n) {
            fa[n] = fmaxf(fmaf(oA[0][n], sc2v[n], bi2v[n]), 0.f);
            fb[n] = fmaxf(fmaf(oN[0][n], sc2v[n], bi2v[n]), 0.f);
        }
        float acc13[13];
        #pragma unroll
        for (int c = 0; c < 13; ++c) acc13[c] = 0.f;
        #pragma unroll
        for (int n = 0; n < 5; ++n) {
            #pragma unroll
            for (int c = 0; c < 13; ++c) {
                float2 wp = g_WLP[(c * 5 + n) * 32 + l];
                acc13[c] += fa[n] * wp.x + fb[n] * wp.y;
            }
        }
        #pragma unroll
        for (int c = 0; c < 13; ++c) acc13[c] = wred(acc13[c]);
        if (l < 13 && bb < B) {
            float ov = 0.f;
            #pragma unroll
            for (int c = 0; c < 13; ++c) if (l == c) ov = acc13[c];
            out[(size_t)bb * 13 + l] = ov + g_CST[32 + l];
        }
    }
}

extern "C" void kernel_launch(void* const* d_in, const int* in_sizes, int n_in,
                              void* d_out, int out_size)
{
    const float* x   = (const float*)d_in[0];
    const float* Wt1 = (const float*)d_in[1];
    const float* a11 = (const float*)d_in[2];
    const float* a21 = (const float*)d_in[3];
    const float* g1  = (const float*)d_in[4];
    const float* b1  = (const float*)d_in[5];
    const float* m1  = (const float*)d_in[6];
    const float* v1  = (const float*)d_in[7];
    const float* Wt2 = (const float*)d_in[8];
    const float* a12 = (const float*)d_in[9];
    const float* a22 = (const float*)d_in[10];
    const float* g2  = (const float*)d_in[11];
    const float* b2  = (const float*)d_in[12];
    const float* m2  = (const float*)d_in[13];
    const float* v2  = (const float*)d_in[14];
    const float* Wl  = (const float*)d_in[15];
    const float* bl  = (const float*)d_in[16];

    int B = in_sizes[0] / 1250;
    prep<<<1, 1024>>>(Wt1, a11, a21, Wt2, a12, a22, Wl, bl,
                      g1, b1, m1, v1, g2, b2, m2, v2);
    int grid = (B + GROUP - 1) / GROUP;
    cudaFuncSetAttribute(gat6_kernel, cudaFuncAttributeMaxDynamicSharedMemorySize, SMEM_BYTES);
    cudaFuncSetAttribute(gat6_kernel, cudaFuncAttributePreferredSharedMemoryCarveout, 100);
    gat6_kernel<<<grid, NTHR, SMEM_BYTES>>>(x, (float*)d_out, B);
}